// round 13
// baseline (speedup 1.0000x reference)
#include <cuda_runtime.h>
#include <math.h>

#define ONE_THIRD2  (2.0f / 3.0f)
#define FOUR_THIRDS (4.0f / 3.0f)
#define LCAP        192

// Scratch (no allocations allowed)
__device__ float g_part[4096];   // per-block partial sums of NN distance

// ---------------------------------------------------------------------------
// Cubic spline weight (matches reference piecewise formula + support mask)
// ---------------------------------------------------------------------------
__device__ __forceinline__ float cubic_w(float q) {
    float w;
    if (q <= 0.5f) w = ONE_THIRD2 + 4.f * q * q * (q - 1.f);
    else           w = FOUR_THIRDS + q * (-4.f + q * (4.f - FOUR_THIRDS * q));
    return (q <= 1.f) ? w : 0.f;
}

// ---------------------------------------------------------------------------
// Kernel 0: pure zero-fill of the whole output. No logic, no barriers, no
// dependencies — plain .wb float4 stores (NOT .cs: graph replays rewrite the
// same addresses, so dirty lines re-dirty in L2 and skip DRAM writeback).
// ---------------------------------------------------------------------------
__global__ __launch_bounds__(256) void zero_fill(float* __restrict__ out, size_t total) {
    const size_t nv = total >> 2;                 // float4 count
    float4* o4 = (float4*)out;
    const float4 z = make_float4(0.f, 0.f, 0.f, 0.f);
    const size_t stride = (size_t)gridDim.x * 256;
    for (size_t i = (size_t)blockIdx.x * 256 + threadIdx.x; i < nv; i += stride)
        o4[i] = z;
    // tail (total not multiple of 4)
    if (blockIdx.x == 0 && threadIdx.x < (total & 3))
        out[(nv << 2) + threadIdx.x] = 0.f;
}

// ---------------------------------------------------------------------------
// Kernel 1: warp-per-node NN distance (proven). Block writes deterministic
// sum of its distances to g_part[blockIdx].
// ---------------------------------------------------------------------------
__global__ __launch_bounds__(256) void min_dist_kernel(const float2* __restrict__ nodes, int N) {
    __shared__ float s_d[8];
    const int tid  = threadIdx.x;
    const int lane = tid & 31;
    const int wid  = tid >> 5;
    const int N2   = N >> 1;
    const float4* n4 = (const float4*)nodes;

    float dsum = 0.f;
    for (int i = blockIdx.x * 8 + wid; i < N; i += gridDim.x * 8) {
        const float2 xi = __ldg(&nodes[i]);
        float m0 = 3.4e38f, m1 = 3.4e38f;
        for (int jj = lane; jj < N2; jj += 32) {
            const float4 v = __ldg(&n4[jj]);
            const int j0 = jj * 2;
            float dx0 = xi.x - v.x, dy0 = xi.y - v.y;
            float dx1 = xi.x - v.z, dy1 = xi.y - v.w;
            float d0 = fmaf(dx0, dx0, dy0 * dy0);
            float d1 = fmaf(dx1, dx1, dy1 * dy1);
            if (j0     != i) m0 = fminf(m0, d0);
            if (j0 + 1 != i) m1 = fminf(m1, d1);
        }
        if ((N & 1) && lane == 0 && (N - 1) != i) {
            float2 p = __ldg(&nodes[N - 1]);
            float dx = xi.x - p.x, dy = xi.y - p.y;
            m0 = fminf(m0, fmaf(dx, dx, dy * dy));
        }
        float m = fminf(m0, m1);
        #pragma unroll
        for (int o = 16; o; o >>= 1) m = fminf(m, __shfl_xor_sync(0xffffffffu, m, o));
        if (lane == 0) dsum += sqrtf(m);
    }
    if (lane == 0) s_d[wid] = dsum;
    __syncthreads();
    if (tid == 0) {
        float s = 0.f;
        #pragma unroll
        for (int w = 0; w < 8; w++) s += s_d[w];
        g_part[blockIdx.x] = s;
    }
}

// ---------------------------------------------------------------------------
// Kernel 2: moments + inversion + sparse scatter. One WARP per query row.
// Per block (8 warps): deterministic dilation reduce, then each warp sweeps
// the N nodes once, accumulating the 6-entry moment matrix and collecting
// in-support indices into its smem list; lane 0 does the fp64 adjugate
// inversion (broadcast by shuffle); lanes overwrite only the ~21 nonzero
// output entries. Runs after zero_fill on the same stream.
// ---------------------------------------------------------------------------
__global__ __launch_bounds__(256) void moments_scatter(const float2* __restrict__ x,
                                                       const float2* __restrict__ nodes,
                                                       float* __restrict__ out,
                                                       int B, int N, int nblk) {
    __shared__ float s_red[256];
    __shared__ int   s_list[8][LCAP];
    __shared__ int   s_cnt[8];
    __shared__ float s_p[2];

    const int tid  = threadIdx.x;
    const int lane = tid & 31;
    const int wid  = tid >> 5;

    // ---- deterministic dilation from per-block partials (L2-hot)
    {
        float s = 0.f;
        for (int i = tid; i < nblk; i += 256) s += g_part[i];
        s_red[tid] = s;
        __syncthreads();
        #pragma unroll
        for (int o = 128; o; o >>= 1) {
            if (tid < o) s_red[tid] += s_red[tid + o];
            __syncthreads();
        }
        if (tid == 0) {
            float dil = 2.5f * (s_red[0] / (float)N);
            s_p[0] = 1.f / dil;
            s_p[1] = dil * dil;
        }
        __syncthreads();
    }
    const float inv_dil = s_p[0];
    const float dil2    = s_p[1];

    const int qi = blockIdx.x * 8 + wid;
    if (qi >= B) return;
    const float2 qv = __ldg(&x[qi]);
    if (lane == 0) s_cnt[wid] = 0;
    __syncwarp();

    // ---- sweep: moment matrix + in-support index list
    float a0 = 0.f, a1 = 0.f, a2 = 0.f, a3 = 0.f, a4 = 0.f, a5 = 0.f;
    {
        const float4* n4 = (const float4*)nodes;
        const int N2 = N >> 1;
        for (int jj = lane; jj < N2; jj += 32) {
            const float4 v = __ldg(&n4[jj]);
            {
                float dx = qv.x - v.x, dy = qv.y - v.y;
                float d2 = dx * dx + dy * dy + 1e-10f;
                if (d2 <= dil2) {
                    float w = cubic_w(sqrtf(d2) * inv_dil);
                    a0 += w;
                    a1 = fmaf(w, dx, a1); a2 = fmaf(w, dy, a2);
                    a3 = fmaf(w * dx, dx, a3); a4 = fmaf(w * dx, dy, a4); a5 = fmaf(w * dy, dy, a5);
                    int p = atomicAdd(&s_cnt[wid], 1);
                    if (p < LCAP) s_list[wid][p] = 2 * jj;
                }
            }
            {
                float dx = qv.x - v.z, dy = qv.y - v.w;
                float d2 = dx * dx + dy * dy + 1e-10f;
                if (d2 <= dil2) {
                    float w = cubic_w(sqrtf(d2) * inv_dil);
                    a0 += w;
                    a1 = fmaf(w, dx, a1); a2 = fmaf(w, dy, a2);
                    a3 = fmaf(w * dx, dx, a3); a4 = fmaf(w * dx, dy, a4); a5 = fmaf(w * dy, dy, a5);
                    int p = atomicAdd(&s_cnt[wid], 1);
                    if (p < LCAP) s_list[wid][p] = 2 * jj + 1;
                }
            }
        }
        if ((N & 1) && lane == 0) {
            const int n = N - 1;
            float2 p2 = __ldg(&nodes[n]);
            float dx = qv.x - p2.x, dy = qv.y - p2.y;
            float d2 = dx * dx + dy * dy + 1e-10f;
            if (d2 <= dil2) {
                float w = cubic_w(sqrtf(d2) * inv_dil);
                a0 += w;
                a1 = fmaf(w, dx, a1); a2 = fmaf(w, dy, a2);
                a3 = fmaf(w * dx, dx, a3); a4 = fmaf(w * dx, dy, a4); a5 = fmaf(w * dy, dy, a5);
                int p = atomicAdd(&s_cnt[wid], 1);
                if (p < LCAP) s_list[wid][p] = n;
            }
        }
    }
    #pragma unroll
    for (int o = 16; o; o >>= 1) {
        a0 += __shfl_xor_sync(0xffffffffu, a0, o);
        a1 += __shfl_xor_sync(0xffffffffu, a1, o);
        a2 += __shfl_xor_sync(0xffffffffu, a2, o);
        a3 += __shfl_xor_sync(0xffffffffu, a3, o);
        a4 += __shfl_xor_sync(0xffffffffu, a4, o);
        a5 += __shfl_xor_sync(0xffffffffu, a5, o);
    }

    // ---- fp64 adjugate inversion on lane 0, shuffle broadcast
    float i00, i01, i02, i11, i12, i22;
    if (lane == 0) {
        double a = (double)a0 + 1e-5, bb = (double)a1, c = (double)a2;
        double d = (double)a3 + 1e-5, e  = (double)a4, f = (double)a5 + 1e-5;
        double c00 = d * f - e * e;
        double c01 = c * e - bb * f;
        double c02 = bb * e - c * d;
        double det = a * c00 + bb * c01 + c * c02;
        double id  = 1.0 / det;
        i00 = (float)(c00 * id);
        i01 = (float)(c01 * id);
        i02 = (float)(c02 * id);
        i11 = (float)((a * f - c * c) * id);
        i12 = (float)((bb * c - a * e) * id);
        i22 = (float)((a * d - bb * bb) * id);
    }
    i00 = __shfl_sync(0xffffffffu, i00, 0);
    i01 = __shfl_sync(0xffffffffu, i01, 0);
    i02 = __shfl_sync(0xffffffffu, i02, 0);
    i11 = __shfl_sync(0xffffffffu, i11, 0);
    i12 = __shfl_sync(0xffffffffu, i12, 0);
    i22 = __shfl_sync(0xffffffffu, i22, 0);
    __syncwarp();

    const size_t BN = (size_t)B * (size_t)N;
    float* __restrict__ o0 = out + (size_t)qi * (size_t)N;
    float* __restrict__ o1 = o0 + BN;
    float* __restrict__ o2 = o1 + BN;
    const int cnt = s_cnt[wid];

    // ---- sparse scatter (or full-row fallback on overflow)
    if (cnt <= LCAP) {
        for (int k = lane; k < cnt; k += 32) {
            const int n = s_list[wid][k];
            const float2 nd = __ldg(&nodes[n]);
            float dx = qv.x - nd.x;
            float dy = qv.y - nd.y;
            float d2 = dx * dx + dy * dy + 1e-10f;
            float w = cubic_w(sqrtf(d2) * inv_dil);
            o0[n] =  w * (i00 + i01 * dx + i02 * dy);
            o1[n] = -(w * (i01 + i11 * dx + i12 * dy));
            o2[n] = -(w * (i02 + i12 * dx + i22 * dy));
        }
    } else {
        for (int n = lane; n < N; n += 32) {
            const float2 nd = __ldg(&nodes[n]);
            float dx = qv.x - nd.x;
            float dy = qv.y - nd.y;
            float d2 = dx * dx + dy * dy + 1e-10f;
            if (d2 <= dil2) {
                float w = cubic_w(sqrtf(d2) * inv_dil);
                o0[n] =  w * (i00 + i01 * dx + i02 * dy);
                o1[n] = -(w * (i01 + i11 * dx + i12 * dy));
                o2[n] = -(w * (i02 + i12 * dx + i22 * dy));
            }
        }
    }
}

// ---------------------------------------------------------------------------
// Launch: metadata order is {x, nodes}; output is [3, B, N] fp32.
// ---------------------------------------------------------------------------
extern "C" void kernel_launch(void* const* d_in, const int* in_sizes, int n_in,
                              void* d_out, int out_size) {
    const float2* x     = (const float2*)d_in[0];
    const float2* nodes = (const float2*)d_in[1];
    float* out = (float*)d_out;
    const int B = in_sizes[0] / 2;
    const int N = in_sizes[1] / 2;

    // 0) zero everything (memset-rate streaming)
    const size_t total = (size_t)out_size;
    int zb = (int)((total / 4 + 255) / 256);
    if (zb > 12288) zb = 12288;
    zero_fill<<<zb, 256>>>(out, total);

    // 1) nearest-neighbor partial sums
    int nblk = (N + 7) / 8;
    if (nblk > 4096) nblk = 4096;
    min_dist_kernel<<<nblk, 256>>>(nodes, N);

    // 2) moments + inversion + sparse scatter (after zeros on same stream)
    moments_scatter<<<(B + 7) / 8, 256>>>(x, nodes, out, B, N, nblk);
}

// round 14
// speedup vs baseline: 1.1065x; 1.1065x over previous
#include <cuda_runtime.h>
#include <math.h>
#include <stdint.h>

#define ONE_THIRD2  (2.0f / 3.0f)
#define FOUR_THIRDS (4.0f / 3.0f)
#define LCAP        192

// Scratch (no allocations allowed)
__device__ float g_part[4096];   // per-block partial sums of NN distance

// ---------------------------------------------------------------------------
// Cubic spline weight (matches reference piecewise formula + support mask)
// ---------------------------------------------------------------------------
__device__ __forceinline__ float cubic_w(float q) {
    float w;
    if (q <= 0.5f) w = ONE_THIRD2 + 4.f * q * q * (q - 1.f);
    else           w = FOUR_THIRDS + q * (-4.f + q * (4.f - FOUR_THIRDS * q));
    return (q <= 1.f) ? w : 0.f;
}

// ===========================================================================
// FAST PATH (N multiple of 128, N<=4096)
// ===========================================================================

// ---------------------------------------------------------------------------
// Kernel 1 (fast): NN distance, 2 nodes per warp sharing each loaded float4
// (halves load count, 4 independent min chains for ILP). Block covers 16
// nodes; writes deterministic sum to g_part[blockIdx]. nblk = N/16.
// ---------------------------------------------------------------------------
__global__ __launch_bounds__(256) void min_dist2(const float2* __restrict__ nodes, int N) {
    __shared__ float s_d[8];
    const int tid  = threadIdx.x;
    const int lane = tid & 31;
    const int wid  = tid >> 5;
    const int half = N >> 1;
    const int N2   = N >> 1;             // float4 count
    const float4* n4 = (const float4*)nodes;

    const int i0 = blockIdx.x * 8 + wid;   // in [0, N/2)
    const int i1 = i0 + half;
    const float2 xa = __ldg(&nodes[i0]);
    const float2 xb = __ldg(&nodes[i1]);

    float mA0 = 3.4e38f, mA1 = 3.4e38f, mB0 = 3.4e38f, mB1 = 3.4e38f;
    #pragma unroll 4
    for (int jj = lane; jj < N2; jj += 32) {
        const float4 v = __ldg(&n4[jj]);
        const int j0 = jj * 2, j1 = j0 + 1;
        float ax0 = xa.x - v.x, ay0 = xa.y - v.y;
        float ax1 = xa.x - v.z, ay1 = xa.y - v.w;
        float bx0 = xb.x - v.x, by0 = xb.y - v.y;
        float bx1 = xb.x - v.z, by1 = xb.y - v.w;
        float dA0 = fmaf(ax0, ax0, ay0 * ay0);
        float dA1 = fmaf(ax1, ax1, ay1 * ay1);
        float dB0 = fmaf(bx0, bx0, by0 * by0);
        float dB1 = fmaf(bx1, bx1, by1 * by1);
        if (j0 != i0) mA0 = fminf(mA0, dA0);
        if (j1 != i0) mA1 = fminf(mA1, dA1);
        if (j0 != i1) mB0 = fminf(mB0, dB0);
        if (j1 != i1) mB1 = fminf(mB1, dB1);
    }
    float mA = fminf(mA0, mA1);
    float mB = fminf(mB0, mB1);
    #pragma unroll
    for (int o = 16; o; o >>= 1) {
        mA = fminf(mA, __shfl_xor_sync(0xffffffffu, mA, o));
        mB = fminf(mB, __shfl_xor_sync(0xffffffffu, mB, o));
    }
    if (lane == 0) s_d[wid] = sqrtf(mA) + sqrtf(mB);
    __syncthreads();
    if (tid == 0) {
        float s = 0.f;
        #pragma unroll
        for (int w = 0; w < 8; w++) s += s_d[w];
        g_part[blockIdx.x] = s;
    }
}

// ---------------------------------------------------------------------------
// Kernel 2 (fast): warp-owns-row RKPM. NO block barriers anywhere.
// Per warp: deterministic dilation reduce -> moment sweep + in-support bitmap
// (smem atomicOr) -> lane-0 fp64 adjugate inversion -> single output pass:
// 4 nodes/lane/iter, bitmap says zero (store z4 x3) or compute (rare).
// Warps stay phase-staggered so the store stream never pauses.
// ---------------------------------------------------------------------------
__global__ __launch_bounds__(256) void rkpm_warp(const float2* __restrict__ x,
                                                 const float2* __restrict__ nodes,
                                                 float* __restrict__ out,
                                                 int B, int N, int nblk) {
    __shared__ uint32_t s_bm[8][128];   // per-warp bitmap, 4096 bits

    const int tid  = threadIdx.x;
    const int lane = tid & 31;
    const int wid  = tid >> 5;

    // ---- per-warp deterministic dilation (identical order in every warp)
    float s = 0.f;
    for (int i = lane; i < nblk; i += 32) s += g_part[i];
    #pragma unroll
    for (int o = 16; o; o >>= 1) s += __shfl_xor_sync(0xffffffffu, s, o);
    const float dil     = 2.5f * (s / (float)N);
    const float inv_dil = 1.f / dil;
    const float dil2    = dil * dil;

    const int qi = blockIdx.x * 8 + wid;
    if (qi >= B) return;
    const float2 qv = __ldg(&x[qi]);

    // ---- zero bitmap
    #pragma unroll
    for (int k = lane; k < 128; k += 32) s_bm[wid][k] = 0;
    __syncwarp();

    // ---- sweep: moments + bitmap
    float a0 = 0.f, a1 = 0.f, a2 = 0.f, a3 = 0.f, a4 = 0.f, a5 = 0.f;
    {
        const float4* n4 = (const float4*)nodes;
        const int N2 = N >> 1;
        for (int jj = lane; jj < N2; jj += 32) {
            const float4 v = __ldg(&n4[jj]);
            {
                float dx = qv.x - v.x, dy = qv.y - v.y;
                float d2 = dx * dx + dy * dy + 1e-10f;
                if (d2 <= dil2) {
                    float w = cubic_w(sqrtf(d2) * inv_dil);
                    a0 += w;
                    a1 = fmaf(w, dx, a1); a2 = fmaf(w, dy, a2);
                    a3 = fmaf(w * dx, dx, a3); a4 = fmaf(w * dx, dy, a4); a5 = fmaf(w * dy, dy, a5);
                    int n = 2 * jj;
                    atomicOr(&s_bm[wid][n >> 5], 1u << (n & 31));
                }
            }
            {
                float dx = qv.x - v.z, dy = qv.y - v.w;
                float d2 = dx * dx + dy * dy + 1e-10f;
                if (d2 <= dil2) {
                    float w = cubic_w(sqrtf(d2) * inv_dil);
                    a0 += w;
                    a1 = fmaf(w, dx, a1); a2 = fmaf(w, dy, a2);
                    a3 = fmaf(w * dx, dx, a3); a4 = fmaf(w * dx, dy, a4); a5 = fmaf(w * dy, dy, a5);
                    int n = 2 * jj + 1;
                    atomicOr(&s_bm[wid][n >> 5], 1u << (n & 31));
                }
            }
        }
    }
    #pragma unroll
    for (int o = 16; o; o >>= 1) {
        a0 += __shfl_xor_sync(0xffffffffu, a0, o);
        a1 += __shfl_xor_sync(0xffffffffu, a1, o);
        a2 += __shfl_xor_sync(0xffffffffu, a2, o);
        a3 += __shfl_xor_sync(0xffffffffu, a3, o);
        a4 += __shfl_xor_sync(0xffffffffu, a4, o);
        a5 += __shfl_xor_sync(0xffffffffu, a5, o);
    }

    // ---- fp64 adjugate inversion (lane 0) + broadcast
    float i00, i01, i02, i11, i12, i22;
    if (lane == 0) {
        double a = (double)a0 + 1e-5, bb = (double)a1, c = (double)a2;
        double d = (double)a3 + 1e-5, e  = (double)a4, f = (double)a5 + 1e-5;
        double c00 = d * f - e * e;
        double c01 = c * e - bb * f;
        double c02 = bb * e - c * d;
        double det = a * c00 + bb * c01 + c * c02;
        double id  = 1.0 / det;
        i00 = (float)(c00 * id);
        i01 = (float)(c01 * id);
        i02 = (float)(c02 * id);
        i11 = (float)((a * f - c * c) * id);
        i12 = (float)((bb * c - a * e) * id);
        i22 = (float)((a * d - bb * bb) * id);
    }
    i00 = __shfl_sync(0xffffffffu, i00, 0);
    i01 = __shfl_sync(0xffffffffu, i01, 0);
    i02 = __shfl_sync(0xffffffffu, i02, 0);
    i11 = __shfl_sync(0xffffffffu, i11, 0);
    i12 = __shfl_sync(0xffffffffu, i12, 0);
    i22 = __shfl_sync(0xffffffffu, i22, 0);
    __syncwarp();

    // ---- single output pass: mostly pure z4 stores, rare recompute
    const size_t BN = (size_t)B * (size_t)N;
    float* __restrict__ o0 = out + (size_t)qi * (size_t)N;
    float* __restrict__ o1 = o0 + BN;
    float* __restrict__ o2 = o1 + BN;
    const float4 z4 = make_float4(0.f, 0.f, 0.f, 0.f);
    const uint32_t* bm = s_bm[wid];
    const int iters = N >> 7;               // 128 n per warp-iteration

    for (int it = 0; it < iters; it++) {
        const int n0 = it * 128 + lane * 4;
        const uint32_t word = bm[n0 >> 5];
        const uint32_t bits = (word >> (n0 & 31)) & 0xFu;
        float4 r0 = z4, r1 = z4, r2 = z4;
        if (bits) {
            const float4 nA = __ldg((const float4*)(nodes + n0));
            const float4 nB = __ldg((const float4*)(nodes + n0 + 2));
            const float ndx[4] = {nA.x, nA.z, nB.x, nB.z};
            const float ndy[4] = {nA.y, nA.w, nB.y, nB.w};
            float rp[4], rx[4], ry[4];
            #pragma unroll
            for (int j = 0; j < 4; j++) {
                float dx = qv.x - ndx[j];
                float dy = qv.y - ndy[j];
                float d2 = dx * dx + dy * dy + 1e-10f;
                if (d2 <= dil2) {
                    float w = cubic_w(sqrtf(d2) * inv_dil);
                    rp[j] =  w * (i00 + i01 * dx + i02 * dy);
                    rx[j] = -(w * (i01 + i11 * dx + i12 * dy));
                    ry[j] = -(w * (i02 + i12 * dx + i22 * dy));
                } else {
                    rp[j] = 0.f; rx[j] = 0.f; ry[j] = 0.f;
                }
            }
            r0 = make_float4(rp[0], rp[1], rp[2], rp[3]);
            r1 = make_float4(rx[0], rx[1], rx[2], rx[3]);
            r2 = make_float4(ry[0], ry[1], ry[2], ry[3]);
        }
        *(float4*)(o0 + n0) = r0;
        *(float4*)(o1 + n0) = r1;
        *(float4*)(o2 + n0) = r2;
    }
}

// ===========================================================================
// GENERIC FALLBACK (any N, B) — R13 pipeline, known correct
// ===========================================================================

__global__ __launch_bounds__(256) void zero_fill(float* __restrict__ out, size_t total) {
    const size_t nv = total >> 2;
    float4* o4 = (float4*)out;
    const float4 z = make_float4(0.f, 0.f, 0.f, 0.f);
    const size_t stride = (size_t)gridDim.x * 256;
    for (size_t i = (size_t)blockIdx.x * 256 + threadIdx.x; i < nv; i += stride)
        o4[i] = z;
    if (blockIdx.x == 0 && threadIdx.x < (total & 3))
        out[(nv << 2) + threadIdx.x] = 0.f;
}

__global__ __launch_bounds__(256) void min_dist_kernel(const float2* __restrict__ nodes, int N) {
    __shared__ float s_d[8];
    const int tid  = threadIdx.x;
    const int lane = tid & 31;
    const int wid  = tid >> 5;
    float dsum = 0.f;
    for (int i = blockIdx.x * 8 + wid; i < N; i += gridDim.x * 8) {
        const float2 xi = __ldg(&nodes[i]);
        float m = 3.4e38f;
        for (int j = lane; j < N; j += 32) {
            const float2 nd = __ldg(&nodes[j]);
            float dx = xi.x - nd.x, dy = xi.y - nd.y;
            float d2 = fmaf(dx, dx, dy * dy);
            if (j != i) m = fminf(m, d2);
        }
        #pragma unroll
        for (int o = 16; o; o >>= 1) m = fminf(m, __shfl_xor_sync(0xffffffffu, m, o));
        if (lane == 0) dsum += sqrtf(m);
    }
    if (lane == 0) s_d[wid] = dsum;
    __syncthreads();
    if (tid == 0) {
        float t = 0.f;
        #pragma unroll
        for (int w = 0; w < 8; w++) t += s_d[w];
        g_part[blockIdx.x] = t;
    }
}

__global__ __launch_bounds__(256) void moments_scatter(const float2* __restrict__ x,
                                                       const float2* __restrict__ nodes,
                                                       float* __restrict__ out,
                                                       int B, int N, int nblk) {
    __shared__ float s_red[256];
    __shared__ int   s_list[8][LCAP];
    __shared__ int   s_cnt[8];
    __shared__ float s_p[2];
    const int tid  = threadIdx.x;
    const int lane = tid & 31;
    const int wid  = tid >> 5;
    {
        float t = 0.f;
        for (int i = tid; i < nblk; i += 256) t += g_part[i];
        s_red[tid] = t;
        __syncthreads();
        #pragma unroll
        for (int o = 128; o; o >>= 1) {
            if (tid < o) s_red[tid] += s_red[tid + o];
            __syncthreads();
        }
        if (tid == 0) {
            float dil = 2.5f * (s_red[0] / (float)N);
            s_p[0] = 1.f / dil;
            s_p[1] = dil * dil;
        }
        __syncthreads();
    }
    const float inv_dil = s_p[0];
    const float dil2    = s_p[1];
    const int qi = blockIdx.x * 8 + wid;
    if (qi >= B) return;
    const float2 qv = __ldg(&x[qi]);
    if (lane == 0) s_cnt[wid] = 0;
    __syncwarp();

    float a0 = 0.f, a1 = 0.f, a2 = 0.f, a3 = 0.f, a4 = 0.f, a5 = 0.f;
    for (int n = lane; n < N; n += 32) {
        const float2 nd = __ldg(&nodes[n]);
        float dx = qv.x - nd.x, dy = qv.y - nd.y;
        float d2 = dx * dx + dy * dy + 1e-10f;
        if (d2 <= dil2) {
            float w = cubic_w(sqrtf(d2) * inv_dil);
            a0 += w;
            a1 = fmaf(w, dx, a1); a2 = fmaf(w, dy, a2);
            a3 = fmaf(w * dx, dx, a3); a4 = fmaf(w * dx, dy, a4); a5 = fmaf(w * dy, dy, a5);
            int p = atomicAdd(&s_cnt[wid], 1);
            if (p < LCAP) s_list[wid][p] = n;
        }
    }
    #pragma unroll
    for (int o = 16; o; o >>= 1) {
        a0 += __shfl_xor_sync(0xffffffffu, a0, o);
        a1 += __shfl_xor_sync(0xffffffffu, a1, o);
        a2 += __shfl_xor_sync(0xffffffffu, a2, o);
        a3 += __shfl_xor_sync(0xffffffffu, a3, o);
        a4 += __shfl_xor_sync(0xffffffffu, a4, o);
        a5 += __shfl_xor_sync(0xffffffffu, a5, o);
    }
    float i00, i01, i02, i11, i12, i22;
    if (lane == 0) {
        double a = (double)a0 + 1e-5, bb = (double)a1, c = (double)a2;
        double d = (double)a3 + 1e-5, e  = (double)a4, f = (double)a5 + 1e-5;
        double c00 = d * f - e * e;
        double c01 = c * e - bb * f;
        double c02 = bb * e - c * d;
        double det = a * c00 + bb * c01 + c * c02;
        double id  = 1.0 / det;
        i00 = (float)(c00 * id); i01 = (float)(c01 * id); i02 = (float)(c02 * id);
        i11 = (float)((a * f - c * c) * id);
        i12 = (float)((bb * c - a * e) * id);
        i22 = (float)((a * d - bb * bb) * id);
    }
    i00 = __shfl_sync(0xffffffffu, i00, 0);
    i01 = __shfl_sync(0xffffffffu, i01, 0);
    i02 = __shfl_sync(0xffffffffu, i02, 0);
    i11 = __shfl_sync(0xffffffffu, i11, 0);
    i12 = __shfl_sync(0xffffffffu, i12, 0);
    i22 = __shfl_sync(0xffffffffu, i22, 0);
    __syncwarp();

    const size_t BN = (size_t)B * (size_t)N;
    float* __restrict__ o0 = out + (size_t)qi * (size_t)N;
    float* __restrict__ o1 = o0 + BN;
    float* __restrict__ o2 = o1 + BN;
    const int cnt = s_cnt[wid];
    if (cnt <= LCAP) {
        for (int k = lane; k < cnt; k += 32) {
            const int n = s_list[wid][k];
            const float2 nd = __ldg(&nodes[n]);
            float dx = qv.x - nd.x, dy = qv.y - nd.y;
            float d2 = dx * dx + dy * dy + 1e-10f;
            float w = cubic_w(sqrtf(d2) * inv_dil);
            o0[n] =  w * (i00 + i01 * dx + i02 * dy);
            o1[n] = -(w * (i01 + i11 * dx + i12 * dy));
            o2[n] = -(w * (i02 + i12 * dx + i22 * dy));
        }
    } else {
        for (int n = lane; n < N; n += 32) {
            const float2 nd = __ldg(&nodes[n]);
            float dx = qv.x - nd.x, dy = qv.y - nd.y;
            float d2 = dx * dx + dy * dy + 1e-10f;
            if (d2 <= dil2) {
                float w = cubic_w(sqrtf(d2) * inv_dil);
                o0[n] =  w * (i00 + i01 * dx + i02 * dy);
                o1[n] = -(w * (i01 + i11 * dx + i12 * dy));
                o2[n] = -(w * (i02 + i12 * dx + i22 * dy));
            }
        }
    }
}

// ---------------------------------------------------------------------------
// Launch: metadata order is {x, nodes}; output is [3, B, N] fp32.
// ---------------------------------------------------------------------------
extern "C" void kernel_launch(void* const* d_in, const int* in_sizes, int n_in,
                              void* d_out, int out_size) {
    const float2* x     = (const float2*)d_in[0];
    const float2* nodes = (const float2*)d_in[1];
    float* out = (float*)d_out;
    const int B = in_sizes[0] / 2;
    const int N = in_sizes[1] / 2;

    if (N <= 4096 && (N & 127) == 0) {
        // fast path: warp-owns-row
        const int nblk = N / 16;                       // min_dist2 blocks
        min_dist2<<<nblk, 256>>>(nodes, N);
        rkpm_warp<<<(B + 7) / 8, 256>>>(x, nodes, out, B, N, nblk);
    } else {
        // generic fallback (proven correct)
        const size_t total = (size_t)out_size;
        int zb = (int)((total / 4 + 255) / 256);
        if (zb > 12288) zb = 12288;
        zero_fill<<<zb, 256>>>(out, total);
        int nblk = (N + 7) / 8;
        if (nblk > 4096) nblk = 4096;
        min_dist_kernel<<<nblk, 256>>>(nodes, N);
        moments_scatter<<<(B + 7) / 8, 256>>>(x, nodes, out, B, N, nblk);
    }
}